// round 17
// baseline (speedup 1.0000x reference)
#include <cuda_runtime.h>
#include <cuda_bf16.h>
#include <cuda_fp16.h>
#include <cstdint>

#define N_LAYER  4
#define D_MODEL  1024
#define D_STATE  128
#define D_CONV   4
#define HEADDIM  64
#define NHEADS   32
#define D_INNER  2048
#define CONV_DIM 2304         // D_INNER + 2*D_STATE
#define D_IN_PROJ 4384        // 2*D_INNER + 2*D_STATE + NHEADS
#define LSEQ     1024
#define VOCAB    50288
#define EPS      1e-5f

// ---------------- scratch (static device globals; no allocation) -------------
__device__ float g_x  [LSEQ * D_MODEL];
__device__ float g_zx [LSEQ * D_IN_PROJ];
__device__ float g_xbc[LSEQ * CONV_DIM];
__device__ float g_dt [LSEQ * NHEADS];
__device__ float g_y  [LSEQ * D_INNER];
__device__ float g_part[4 * LSEQ * D_MODEL];   // split-K partials (16 MB)

// fp16 storage (raw 16-bit)
__device__ unsigned short g_emb_h [VOCAB * D_MODEL];
__device__ unsigned short g_inw_h [N_LAYER * D_IN_PROJ * D_MODEL];
__device__ unsigned short g_outw_h[N_LAYER * D_MODEL * D_INNER];
__device__ unsigned short g_u_hi  [LSEQ * D_MODEL];
__device__ unsigned short g_u_lo  [LSEQ * D_MODEL];
__device__ unsigned short g_t2_hi [LSEQ * D_INNER];
__device__ unsigned short g_t2_lo [LSEQ * D_INNER];

// ---------------- fp32 -> fp16 (single) ---------------------------------------
__global__ void cvt_half_kernel(const float4* __restrict__ in,
                                __half2* __restrict__ out, int n4) {
    int i = blockIdx.x * blockDim.x + threadIdx.x;
    if (i >= n4) return;
    float4 v = in[i];
    out[2 * i]     = __floats2half2_rn(v.x, v.y);
    out[2 * i + 1] = __floats2half2_rn(v.z, v.w);
}

// ---------------- embedding gather ------------------------------------------
__global__ void embed_kernel(const int* __restrict__ ids,
                             const float* __restrict__ emb,
                             float* __restrict__ x) {
    int idx = blockIdx.x * blockDim.x + threadIdx.x;
    if (idx >= LSEQ * D_MODEL) return;
    int t = idx >> 10;
    int d = idx & 1023;
    x[idx] = emb[(size_t)ids[t] * D_MODEL + d];
}

// ---------------- rmsnorm (optionally gated); outputs fp16 hi/lo -------------
__global__ void rmsnorm_kernel(const float* __restrict__ x, int xs,
                               const float* __restrict__ w,
                               const float* z, int zs,
                               unsigned short* __restrict__ out_hi,
                               unsigned short* __restrict__ out_lo, int D) {
    __shared__ float buf[2048];
    __shared__ float red[8];
    __shared__ float s_scale;
    int t = blockIdx.x;
    int tid = threadIdx.x;

    float ss = 0.f;
    for (int c = tid; c < D; c += blockDim.x) {
        float v = x[(size_t)t * xs + c];
        if (z) {
            float zz = z[(size_t)t * zs + c];
            v *= zz / (1.f + expf(-zz));
        }
        buf[c] = v;
        ss += v * v;
    }
    #pragma unroll
    for (int o = 16; o; o >>= 1) ss += __shfl_xor_sync(0xffffffffu, ss, o);
    if ((tid & 31) == 0) red[tid >> 5] = ss;
    __syncthreads();
    if (tid < 32) {
        float v = (tid < 8) ? red[tid] : 0.f;
        #pragma unroll
        for (int o = 4; o; o >>= 1) v += __shfl_xor_sync(0xffffffffu, v, o);
        if (tid == 0) s_scale = rsqrtf(v / (float)D + EPS);
    }
    __syncthreads();
    float sc = s_scale;
    for (int c = tid; c < D; c += blockDim.x) {
        float v = buf[c] * sc * w[c];
        __half h = __float2half_rn(v);
        __half l = __float2half_rn(v - __half2float(h));
        out_hi[(size_t)t * D + c] = *(unsigned short*)&h;
        out_lo[(size_t)t * D + c] = *(unsigned short*)&l;
    }
}

// ---- fused depthwise conv+silu (c < CONV_DIM) and dt softplus (else) --------
__global__ void convdt_kernel(const float* __restrict__ zx,
                              const float* __restrict__ w,
                              const float* __restrict__ b,
                              const float* __restrict__ dt_bias,
                              float* __restrict__ xbc,
                              float* __restrict__ dt) {
    int idx = blockIdx.x * blockDim.x + threadIdx.x;
    if (idx >= LSEQ * (CONV_DIM + NHEADS)) return;
    int t = idx / (CONV_DIM + NHEADS);
    int c = idx - t * (CONV_DIM + NHEADS);
    if (c < CONV_DIM) {
        float acc = b[c];
        const float* wc = w + c * 4;
        #pragma unroll
        for (int j = 0; j < 4; ++j) {
            int tt = t - 3 + j;
            if (tt >= 0) acc += zx[(size_t)tt * D_IN_PROJ + D_INNER + c] * wc[j];
        }
        xbc[(size_t)t * CONV_DIM + c] = acc / (1.f + expf(-acc));
    } else {
        int h = c - CONV_DIM;
        float v = zx[(size_t)t * D_IN_PROJ + (D_INNER + CONV_DIM) + h] + dt_bias[h];
        dt[t * NHEADS + h] = (v > 20.f) ? v : log1pf(expf(v));
    }
}

// ---- split-K reduction: x += p0 + p1 + p2 + p3 ------------------------------
__global__ void reduce4_kernel(const float4* __restrict__ p,
                               float4* __restrict__ x, int mn4) {
    int i = blockIdx.x * blockDim.x + threadIdx.x;
    if (i >= mn4) return;
    float4 a = p[i];
    float4 b = p[i + mn4];
    float4 c = p[i + 2 * mn4];
    float4 d = p[i + 3 * mn4];
    float4 v = x[i];
    v.x += (a.x + b.x) + (c.x + d.x);
    v.y += (a.y + b.y) + (c.y + d.y);
    v.z += (a.z + b.z) + (c.z + d.z);
    v.w += (a.w + b.w) + (c.w + d.w);
    x[i] = v;
}

__device__ __forceinline__ uint32_t smem_u32(const void* p) {
    return (uint32_t)__cvta_generic_to_shared(p);
}
__device__ __forceinline__ void cpa(uint32_t dst, const void* src, int bytes) {
    if (bytes == 16)
        asm volatile("cp.async.ca.shared.global [%0], [%1], 16;"
                     :: "r"(dst), "l"(src));
    else
        asm volatile("cp.async.ca.shared.global [%0], [%1], 4;"
                     :: "r"(dst), "l"(src));
}

// =============================================================================
// SSD scan, cp.async staged, 16 channels/block (4/warp).
// 128 blocks: h = bid>>2, pbase = (bid&3)*16.  B/C replication 4x (was 8x).
// Scan math and partial-sum order identical to the proven R13 kernel.
// smem: B 2*16*128 + C 2*16*128 + x 2*16*16 + dt 2*16 + P 4*4*16*33
//       = 17,184 floats = 68,736 bytes.
// =============================================================================
#define TB 16
#define SSD_SMEM 68736
__global__ __launch_bounds__(128) void ssd_kernel(
    const float* __restrict__ xbc,
    const float* __restrict__ dt,
    const float* __restrict__ A_log,
    const float* __restrict__ D_p,
    float* __restrict__ y) {
    extern __shared__ float sm[];
    float* sB  = sm;                       // [2][TB][128]
    float* sC  = sB + 2 * TB * 128;        // [2][TB][128]
    float* sx  = sC + 2 * TB * 128;        // [2][TB][16]
    float* sdt = sx + 2 * TB * 16;         // [2][TB]
    float* sPa = sdt + 2 * TB;             // [4][4*TB*33]

    int tid  = threadIdx.x;
    int wib  = tid >> 5;
    int lane = tid & 31;
    int h     = blockIdx.x >> 2;           // head
    int pbase = (blockIdx.x & 3) * 16;     // block's 16-channel base
    int pw    = pbase + wib * 4;           // warp's 4-channel base

    float* P = sPa + wib * (4 * TB * 33);

    #define SSD_STAGE(t0, s) do {                                              \
        const float* base = xbc + (size_t)(t0) * CONV_DIM;                     \
        uint32_t dB = smem_u32(sB + (s) * TB * 128);                           \
        uint32_t dC = smem_u32(sC + (s) * TB * 128);                           \
        _Pragma("unroll")                                                      \
        for (int c = 0; c < 4; ++c) {                                          \
            int ch  = tid + c * 128;                                           \
            int row = ch >> 5;                                                 \
            int col = (ch & 31) * 4;                                           \
            const float* rp = base + (size_t)row * CONV_DIM;                   \
            cpa(dB + (uint32_t)(row * 128 + col) * 4, rp + D_INNER + col, 16); \
            cpa(dC + (uint32_t)(row * 128 + col) * 4,                          \
                rp + D_INNER + D_STATE + col, 16);                             \
        }                                                                      \
        if (tid < 64) {                                                        \
            int row = tid >> 2, col = (tid & 3) * 4;                           \
            cpa(smem_u32(sx + (s) * TB * 16 + row * 16 + col),                 \
                base + (size_t)row * CONV_DIM + h * HEADDIM + pbase + col, 16);\
        }                                                                      \
        if (tid < TB)                                                          \
            cpa(smem_u32(sdt + (s) * TB + tid),                                \
                dt + (size_t)(t0 + tid) * NHEADS + h, 4);                      \
    } while (0)

    float Ah = -expf(A_log[h]);
    float Dh = D_p[h];
    float dsel = (lane == 0) ? Dh : 0.f;

    float st[4][4];
    #pragma unroll
    for (int c = 0; c < 4; ++c)
        #pragma unroll
        for (int n = 0; n < 4; ++n) st[c][n] = 0.f;

    SSD_STAGE(0, 0);
    asm volatile("cp.async.commit_group;");
    asm volatile("cp.async.wait_group 0;");
    __syncthreads();

    for (int t0 = 0; t0 < LSEQ; t0 += TB) {
        int cur = (t0 >> 4) & 1;
        if (t0 + TB < LSEQ) {
            SSD_STAGE(t0 + TB, cur ^ 1);
        }
        asm volatile("cp.async.commit_group;");

        const float* bB = sB + cur * TB * 128;
        const float* bC = sC + cur * TB * 128;
        const float* bx = sx + cur * TB * 16;
        const float* bd = sdt + cur * TB;

        #pragma unroll
        for (int tt = 0; tt < TB; ++tt) {
            float dtv = bd[tt];
            float e   = __expf(Ah * dtv);
            float4 Bv = *(const float4*)(bB + tt * 128 + lane * 4);
            float4 Cv = *(const float4*)(bC + tt * 128 + lane * 4);
            #pragma unroll
            for (int c = 0; c < 4; ++c) {
                float xv = bx[tt * 16 + wib * 4 + c];
                float xd = xv * dtv;
                st[c][0] = e * st[c][0] + Bv.x * xd;
                st[c][1] = e * st[c][1] + Bv.y * xd;
                st[c][2] = e * st[c][2] + Bv.z * xd;
                st[c][3] = e * st[c][3] + Bv.w * xd;
                P[(c * TB + tt) * 33 + lane] =
                    Cv.x * st[c][0] + Cv.y * st[c][1] +
                    Cv.z * st[c][2] + Cv.w * st[c][3] + xv * dsel;
            }
        }
        __syncwarp();
        // reduction: 2 rounds; lane covers (ch, tt) with ch = (lane>>4)+2r
        #pragma unroll
        for (int r = 0; r < 2; ++r) {
            int ch  = (lane >> 4) + 2 * r;
            int tt_ = lane & 15;
            const float* rr = P + (ch * TB + tt_) * 33;
            float s0 = 0.f, s1 = 0.f;
            #pragma unroll
            for (int j = 0; j < 32; j += 2) {
                s0 += rr[j];
                s1 += rr[j + 1];
            }
            y[(size_t)(t0 + tt_) * D_INNER + h * HEADDIM + pw + ch] = s0 + s1;
        }
        asm volatile("cp.async.wait_group 0;");
        __syncthreads();
    }
}

// =============================================================================
// fp16 split-precision tensor-core GEMM (NT), 2-stage cp.async double buffer,
// B fragments via ldmatrix.x4.
// =============================================================================
#define BM 128

#define LDSM4(R, addr) asm volatile( \
    "ldmatrix.sync.aligned.m8n8.x4.shared.b16 {%0,%1,%2,%3}, [%4];" \
    : "=r"((R)[0]),"=r"((R)[1]),"=r"((R)[2]),"=r"((R)[3]) : "r"(addr))

__device__ __forceinline__ void mma_f16(float* acc, const uint32_t* a,
                                        const uint32_t* b) {
    asm volatile(
        "mma.sync.aligned.m16n8k16.row.col.f32.f16.f16.f32 "
        "{%0,%1,%2,%3},{%4,%5,%6,%7},{%8,%9},{%0,%1,%2,%3};"
        : "+f"(acc[0]), "+f"(acc[1]), "+f"(acc[2]), "+f"(acc[3])
        : "r"(a[0]), "r"(a[1]), "r"(a[2]), "r"(a[3]), "r"(b[0]), "r"(b[1]));
}

template<int BNT, int NPASS, int BK>
__global__ __launch_bounds__(256) void gemm_mma(
    const unsigned short* __restrict__ Ahi, const unsigned short* __restrict__ Alo,
    const unsigned short* __restrict__ Bh,
    const float* add, float* __restrict__ C,
    int M, int N, int K, int lda, int kof) {
    constexpr int NI    = BNT / 16;
    constexpr int LDSB  = BK + 8;
    constexpr int CHB   = (BNT * BK) / 2048;
    constexpr int A_E   = BM * LDSB;
    constexpr int ALO_E = (NPASS >= 2 ? BM : 0) * LDSB;
    constexpr int B_E   = BNT * LDSB;
    constexpr int STAGE_E = A_E + ALO_E + B_E;

    extern __shared__ unsigned short gsm[];

    int z = blockIdx.z;
    Ahi += (size_t)z * kof;
    Alo += (size_t)z * kof;
    Bh  += (size_t)z * kof;
    C   += (size_t)z * M * (size_t)N;

    int tid  = threadIdx.x;
    int wid  = tid >> 5, lane = tid & 31;
    int wm   = wid & 3;
    int wn   = wid >> 2;
    int bm   = blockIdx.x * BM;
    int bn   = blockIdx.y * BNT;

    float acc[2][NI][4];
    #pragma unroll
    for (int i = 0; i < 2; ++i)
        #pragma unroll
        for (int j = 0; j < NI; ++j)
            #pragma unroll
            for (int q = 0; q < 4; ++q) acc[i][j][q] = 0.f;

    int lrA = tid >> 1;
    int lkA = (tid & 1) * (BK / 2);
    constexpr int TPR = 256 / BNT;
    int lrB = tid / TPR;
    int lkB = (tid % TPR) * (CHB * 8);
    int brow  = bn + lrB;
    int browc = (brow < N) ? brow : 0;

    const unsigned short* pAh = Ahi + (size_t)(bm + lrA) * lda + lkA;
    const unsigned short* pAl = Alo + (size_t)(bm + lrA) * lda + lkA;
    const unsigned short* pB  = Bh  + (size_t)browc * lda + lkB;

    #define G_ISSUE(kt, s) do {                                                \
        unsigned short* st = gsm + (s) * STAGE_E;                              \
        int ke = (kt) * BK;                                                    \
        _Pragma("unroll")                                                      \
        for (int c = 0; c < BK / 16; ++c)                                      \
            cpa(smem_u32(&st[lrA * LDSB + lkA + c * 8]),                       \
                pAh + ke + c * 8, 16);                                         \
        if (NPASS >= 2) {                                                      \
            _Pragma("unroll")                                                  \
            for (int c = 0; c < BK / 16; ++c)                                  \
                cpa(smem_u32(&st[A_E + lrA * LDSB + lkA + c * 8]),             \
                    pAl + ke + c * 8, 16);                                     \
        }                                                                      \
        _Pragma("unroll")                                                      \
        for (int c = 0; c < CHB; ++c)                                          \
            cpa(smem_u32(&st[A_E + ALO_E + lrB * LDSB + lkB + c * 8]),         \
                pB + ke + c * 8, 16);                                          \
    } while (0)

    int mrow      = wm * 32 + (lane & 15);
    int acol_half = ((lane >> 4) << 3);
    int brow4     = wn * (BNT / 2) + (lane & 7) + ((lane >> 4) << 3);
    int bcol_half = ((lane >> 3) & 1) << 3;

    int T = K / BK;
    G_ISSUE(0, 0);
    asm volatile("cp.async.commit_group;");
    if (T > 1) {
        G_ISSUE(1, 1);
        asm volatile("cp.async.commit_group;");
    }

    for (int it = 0; it < T; ++it) {
        if (it + 1 < T) asm volatile("cp.async.wait_group 1;");
        else            asm volatile("cp.async.wait_group 0;");
        __syncthreads();

        unsigned short* st = gsm + (it & 1) * STAGE_E;
        unsigned short* sAhi = st;
        unsigned short* sAlo = st + A_E;
        unsigned short* sBh  = st + A_E + ALO_E;

        #pragma unroll
        for (int ks = 0; ks < BK / 16; ++ks) {
            int kb = ks * 16;
            uint32_t ahi[2][4], alo[2][4];
            #pragma unroll
            for (int mi = 0; mi < 2; ++mi) {
                int off = (mrow + mi * 16) * LDSB + kb + acol_half;
                LDSM4(ahi[mi], smem_u32(&sAhi[off]));
                if (NPASS >= 2) LDSM4(alo[mi], smem_u32(&sAlo[off]));
            }
            uint32_t bh[NI][2];
            #pragma unroll
            for (int n2 = 0; n2 < NI / 2; ++n2) {
                int off = (brow4 + n2 * 16) * LDSB + kb + bcol_half;
                uint32_t r4[4];
                LDSM4(r4, smem_u32(&sBh[off]));
                bh[2 * n2][0]     = r4[0]; bh[2 * n2][1]     = r4[1];
                bh[2 * n2 + 1][0] = r4[2]; bh[2 * n2 + 1][1] = r4[3];
            }
            #pragma unroll
            for (int mi = 0; mi < 2; ++mi)
                #pragma unroll
                for (int ni = 0; ni < NI; ++ni) {
                    mma_f16(acc[mi][ni], ahi[mi], bh[ni]);
                    if (NPASS >= 2) mma_f16(acc[mi][ni], alo[mi], bh[ni]);
                }
        }
        __syncthreads();
        if (it + 2 < T) {
            G_ISSUE(it + 2, it & 1);
            asm volatile("cp.async.commit_group;");
        }
    }

    // --- epilogue ---
    int g = lane >> 2, t4 = lane & 3;
    #pragma unroll
    for (int mi = 0; mi < 2; ++mi) {
        int r0 = bm + wm * 32 + mi * 16 + g;
        #pragma unroll
        for (int ni = 0; ni < NI; ++ni) {
            int col = bn + wn * (BNT / 2) + ni * 8 + t4 * 2;
            if (col < N) {
                float2 v0 = make_float2(acc[mi][ni][0], acc[mi][ni][1]);
                float2 v1 = make_float2(acc[mi][ni][2], acc[mi][ni][3]);
                if (add) {
                    float2 a0 = *(const float2*)(add + (size_t)r0 * N + col);
                    float2 a1 = *(const float2*)(add + (size_t)(r0 + 8) * N + col);
                    v0.x += a0.x; v0.y += a0.y;
                    v1.x += a1.x; v1.y += a1.y;
                }
                *(float2*)(C + (size_t)r0 * N + col)       = v0;
                *(float2*)(C + (size_t)(r0 + 8) * N + col) = v1;
            }
        }
    }
}

template<int BNT, int NPASS, int BK>
constexpr int gemm_smem() {
    return 2 * (BM * (BK + 8) + (NPASS >= 2 ? BM : 0) * (BK + 8) +
                BNT * (BK + 8)) * 2;
}

// ---------------- orchestration ----------------------------------------------
extern "C" void kernel_launch(void* const* d_in, const int* in_sizes, int n_in,
                              void* d_out, int out_size) {
    const int*   ids       = (const int*)  d_in[0];
    const float* emb       = (const float*)d_in[1];
    const float* norm_ws   = (const float*)d_in[2];
    const float* in_ws     = (const float*)d_in[3];
    const float* conv_ws   = (const float*)d_in[4];
    const float* conv_bs   = (const float*)d_in[5];
    const float* dt_biases = (const float*)d_in[6];
    const float* A_logs    = (const float*)d_in[7];
    const float* Ds        = (const float*)d_in[8];
    const float* gnorm_ws  = (const float*)d_in[9];
    const float* out_ws    = (const float*)d_in[10];
    const float* norm_f_w  = (const float*)d_in[11];
    float* out = (float*)d_out;

    float *x, *zx, *xbc, *dtb, *y, *part;
    cudaGetSymbolAddress((void**)&x,    g_x);
    cudaGetSymbolAddress((void**)&zx,   g_zx);
    cudaGetSymbolAddress((void**)&xbc,  g_xbc);
    cudaGetSymbolAddress((void**)&dtb,  g_dt);
    cudaGetSymbolAddress((void**)&y,    g_y);
    cudaGetSymbolAddress((void**)&part, g_part);

    unsigned short *emb_h, *inw_h, *outw_h, *u_hi, *u_lo, *t2_hi, *t2_lo;
    cudaGetSymbolAddress((void**)&emb_h,  g_emb_h);
    cudaGetSymbolAddress((void**)&inw_h,  g_inw_h);
    cudaGetSymbolAddress((void**)&outw_h, g_outw_h);
    cudaGetSymbolAddress((void**)&u_hi,   g_u_hi);
    cudaGetSymbolAddress((void**)&u_lo,   g_u_lo);
    cudaGetSymbolAddress((void**)&t2_hi,  g_t2_hi);
    cudaGetSymbolAddress((void**)&t2_lo,  g_t2_lo);

    constexpr int SM_IN = gemm_smem<128, 2, 64>();   // 110,592 B
    constexpr int SM_LG = gemm_smem<128, 1, 64>();   //  73,728 B
    cudaFuncSetAttribute(ssd_kernel,
                         cudaFuncAttributeMaxDynamicSharedMemorySize, SSD_SMEM);
    cudaFuncSetAttribute((const void*)gemm_mma<128, 2, 64>,
                         cudaFuncAttributeMaxDynamicSharedMemorySize, SM_IN);
    cudaFuncSetAttribute((const void*)gemm_mma<128, 1, 64>,
                         cudaFuncAttributeMaxDynamicSharedMemorySize, SM_LG);

    // (0) embed
    embed_kernel<<<(LSEQ * D_MODEL + 255) / 256, 256>>>(ids, emb, x);
    // (1) pre-norm layer 0
    rmsnorm_kernel<<<LSEQ, 256>>>(x, D_MODEL, norm_ws, nullptr, 0,
                                  u_hi, u_lo, D_MODEL);
    // (2) cvt in_ws -> fp16
    {
        int n4 = N_LAYER * D_IN_PROJ * D_MODEL / 4;
        cvt_half_kernel<<<(n4 + 255) / 256, 256>>>(
            (const float4*)in_ws, (__half2*)inw_h, n4);
    }
    // (3) in_proj layer 0  <-- profiled slot
    gemm_mma<128, 2, 64><<<dim3(LSEQ / BM, (D_IN_PROJ + 127) / 128), 256, SM_IN>>>(
        u_hi, u_lo, inw_h, nullptr, zx, LSEQ, D_IN_PROJ, D_MODEL, D_MODEL, 0);
    // (4) conv+dt layer 0
    convdt_kernel<<<(LSEQ * (CONV_DIM + NHEADS) + 255) / 256, 256>>>(
        zx, conv_ws, conv_bs, dt_biases, xbc, dtb);
    // (5) SSD layer 0
    ssd_kernel<<<128, 128, SSD_SMEM>>>(xbc, dtb, A_logs, Ds, y);
    // (6) cvt out_ws -> fp16
    {
        int n4 = N_LAYER * D_MODEL * D_INNER / 4;
        cvt_half_kernel<<<(n4 + 255) / 256, 256>>>(
            (const float4*)out_ws, (__half2*)outw_h, n4);
    }
    // (7) cvt emb -> fp16
    {
        int n4 = VOCAB * D_MODEL / 4;
        cvt_half_kernel<<<(n4 + 255) / 256, 256>>>(
            (const float4*)emb, (__half2*)emb_h, n4);
    }

    for (int i = 0; i < N_LAYER; ++i) {
        if (i > 0) {
            rmsnorm_kernel<<<LSEQ, 256>>>(
                x, D_MODEL, norm_ws + (size_t)i * D_MODEL, nullptr, 0,
                u_hi, u_lo, D_MODEL);
            gemm_mma<128, 2, 64><<<dim3(LSEQ / BM, (D_IN_PROJ + 127) / 128), 256, SM_IN>>>(
                u_hi, u_lo, inw_h + (size_t)i * D_IN_PROJ * D_MODEL,
                nullptr, zx, LSEQ, D_IN_PROJ, D_MODEL, D_MODEL, 0);
            convdt_kernel<<<(LSEQ * (CONV_DIM + NHEADS) + 255) / 256, 256>>>(
                zx, conv_ws + (size_t)i * CONV_DIM * D_CONV,
                conv_bs + (size_t)i * CONV_DIM,
                dt_biases + (size_t)i * NHEADS, xbc, dtb);
            ssd_kernel<<<128, 128, SSD_SMEM>>>(
                xbc, dtb, A_logs + (size_t)i * NHEADS, Ds + (size_t)i * NHEADS, y);
        }
        rmsnorm_kernel<<<LSEQ, 256>>>(
            y, D_INNER, gnorm_ws + (size_t)i * D_INNER,
            zx, D_IN_PROJ, t2_hi, t2_lo, D_INNER);
        // out_proj: split-K (z=4 x K=512), BK=64 double-buffered -> partials
        gemm_mma<128, 2, 64><<<dim3(LSEQ / BM, D_MODEL / 128, 4), 256, SM_IN>>>(
            t2_hi, t2_lo, outw_h + (size_t)i * D_MODEL * D_INNER,
            nullptr, part, LSEQ, D_MODEL, 512, D_INNER, 512);
        reduce4_kernel<<<(LSEQ * D_MODEL / 4 + 255) / 256, 256>>>(
            (const float4*)part, (float4*)x, LSEQ * D_MODEL / 4);
    }

    // final norm + fp16 1-pass logits (BK=64, double-buffered)
    rmsnorm_kernel<<<LSEQ, 256>>>(x, D_MODEL, norm_f_w, nullptr, 0,
                                  u_hi, u_lo, D_MODEL);
    gemm_mma<128, 1, 64><<<dim3(LSEQ / BM, (VOCAB + 127) / 128), 256, SM_LG>>>(
        u_hi, u_hi, emb_h, nullptr, out, LSEQ, VOCAB, D_MODEL, D_MODEL, 0);
}